// round 14
// baseline (speedup 1.0000x reference)
#include <cuda_runtime.h>
#include <cuda_bf16.h>
#include <cuda_fp16.h>
#include <math.h>
#include <stdint.h>

#define BATCH 16
#define NSEQ  200
#define DDIM  2048
#define HDIM  2048
#define MTOT  (BATCH*NSEQ)          // 3200
#define MK    (MTOT*DDIM)
#define KN    (DDIM*HDIM)
#define KCAT  4096                  // scores concatenated K
#define KOUT  224                   // out GEMM K (200 padded)
#define BNN   (BATCH*NSEQ*NSEQ)

// ---------------- scratch (device globals) ---------------------------------
__device__ float g_q1[BATCH*NSEQ*HDIM];
__device__ float g_q2[BATCH*NSEQ*HDIM];
__device__ float g_lk[BATCH*NSEQ*HDIM];
__device__ float g_kloc[BATCH*NSEQ*HDIM];
__device__ float g_lv[BATCH*NSEQ*HDIM];
__device__ float g_scoresP[4*BNN];      // split-K partial scores

// fragment-packed fp16 operands for projections.
__device__ __align__(16) __half gAh[4*MK];
__device__ __align__(16) __half gWh[5*KN];

// scores/out fp16 hi/lo split operands
__device__ __align__(16) __half gQc_hi[BATCH*NSEQ*KCAT];
__device__ __align__(16) __half gQc_lo[BATCH*NSEQ*KCAT];
__device__ __align__(16) __half gKc_hi[BATCH*NSEQ*KCAT];
__device__ __align__(16) __half gKc_lo[BATCH*NSEQ*KCAT];
__device__ __align__(16) __half gAttn_hi[BATCH*NSEQ*KOUT];
__device__ __align__(16) __half gAttn_lo[BATCH*NSEQ*KOUT];
__device__ __align__(16) __half gLvT_hi[BATCH*HDIM*KOUT];
__device__ __align__(16) __half gLvT_lo[BATCH*HDIM*KOUT];

// ============================ helpers ======================================
__device__ __forceinline__ uint32_t smem_u32(const void* p) {
    uint32_t a;
    asm("{ .reg .u64 t; cvta.to.shared.u64 t, %1; cvt.u32.u64 %0, t; }"
        : "=r"(a) : "l"(p));
    return a;
}
__device__ __forceinline__ void cp16(uint32_t dst, const void* src) {
    asm volatile("cp.async.cg.shared.global [%0], [%1], 16;" :: "r"(dst), "l"(src));
}
#define CP_COMMIT() asm volatile("cp.async.commit_group;" ::: "memory")
#define CP_WAIT1()  asm volatile("cp.async.wait_group 1;" ::: "memory")
#define CP_WAIT0()  asm volatile("cp.async.wait_group 0;" ::: "memory")

__device__ __forceinline__ void ldx4(uint32_t addr, uint32_t& r0, uint32_t& r1,
                                     uint32_t& r2, uint32_t& r3) {
    asm volatile("ldmatrix.sync.aligned.m8n8.x4.shared.b16 {%0,%1,%2,%3}, [%4];"
                 : "=r"(r0), "=r"(r1), "=r"(r2), "=r"(r3) : "r"(addr));
}
// fp16 m16n8k16 (array-operand form, used by scores/out)
__device__ __forceinline__ void mma16816(float* c, const uint32_t* a,
                                         const uint32_t* b) {
    asm volatile(
        "mma.sync.aligned.m16n8k16.row.col.f32.f16.f16.f32 "
        "{%0,%1,%2,%3}, {%4,%5,%6,%7}, {%8,%9}, {%0,%1,%2,%3};"
        : "+f"(c[0]), "+f"(c[1]), "+f"(c[2]), "+f"(c[3])
        : "r"(a[0]), "r"(a[1]), "r"(a[2]), "r"(a[3]), "r"(b[0]), "r"(b[1]));
}
// fp16 m16n8k16 (vector-operand form, used by proj)
__device__ __forceinline__ void mma16816h(float* c, const uint4 a,
                                          const uint2 b) {
    asm volatile(
        "mma.sync.aligned.m16n8k16.row.col.f32.f16.f16.f32 "
        "{%0,%1,%2,%3}, {%4,%5,%6,%7}, {%8,%9}, {%0,%1,%2,%3};"
        : "+f"(c[0]), "+f"(c[1]), "+f"(c[2]), "+f"(c[3])
        : "r"(a.x), "r"(a.y), "r"(a.z), "r"(a.w), "r"(b.x), "r"(b.y));
}
__device__ __forceinline__ void split_f16(float x, __half& h, __half& l) {
    h = __float2half_rn(x);
    l = __float2half_rn(x - __half2float(h));
}

// =================== conversion kernels (fp16 fragment packing) ============
struct ConvAP { const float* src[4]; };
__global__ __launch_bounds__(256) void convA_kernel(ConvAP P)
{
    const int mat = blockIdx.z;
    const int T   = blockIdx.x;
    const int t   = threadIdx.x;
    const int c   = blockIdx.y * 2 + (t >> 7);     // chunk (K=64)
    const int g   = t & 127;
    const int ks  = g >> 5;                        // k-step (K=16)
    const int lane = g & 31;
    const int gq = lane >> 2, tq = lane & 3;
    const float* src = P.src[mat];

    const size_t r0 = (size_t)(T * 16 + gq) * DDIM;
    const size_t r8 = r0 + 8 * DDIM;
    const int k0 = c * 64 + ks * 16 + tq * 2;

    __half2 h0 = __floats2half2_rn(src[r0 + k0],     src[r0 + k0 + 1]);
    __half2 h1 = __floats2half2_rn(src[r8 + k0],     src[r8 + k0 + 1]);
    __half2 h2 = __floats2half2_rn(src[r0 + k0 + 8], src[r0 + k0 + 9]);
    __half2 h3 = __floats2half2_rn(src[r8 + k0 + 8], src[r8 + k0 + 9]);
    uint4 v;
    v.x = *(uint32_t*)&h0; v.y = *(uint32_t*)&h1;
    v.z = *(uint32_t*)&h2; v.w = *(uint32_t*)&h3;

    *(uint4*)(gAh + (size_t)mat * MK +
              (((size_t)(T * 32 + c) * 4 + ks) * 256 + lane * 8)) = v;
}

struct ConvWP { const float* src[5]; };
__global__ __launch_bounds__(256) void convW_kernel(ConvWP P)
{
    const int w  = blockIdx.z;
    const int T8 = blockIdx.x;
    const int t  = threadIdx.x;
    const int c  = blockIdx.y * 2 + (t >> 7);
    const int g  = t & 127;
    const int ks = g >> 5;
    const int lane = g & 31;
    const int gq = lane >> 2, tq = lane & 3;
    const float* W = P.src[w];

    const int n  = T8 * 8 + gq;
    const int k0 = c * 64 + ks * 16 + tq * 2;
    __half2 b0 = __floats2half2_rn(W[(size_t)k0 * HDIM + n],
                                   W[(size_t)(k0 + 1) * HDIM + n]);
    __half2 b1 = __floats2half2_rn(W[(size_t)(k0 + 8) * HDIM + n],
                                   W[(size_t)(k0 + 9) * HDIM + n]);
    uint2 v;
    v.x = *(uint32_t*)&b0; v.y = *(uint32_t*)&b1;
    *(uint2*)(gWh + (size_t)w * KN +
              (((size_t)(T8 * 32 + c) * 4 + ks) * 128 + lane * 4)) = v;
}

// =================== FP16 projection GEMM ==================================
// C[3200,2048] = A @ Wt^T + bias.  BM=128 x BN=256, K-chunk 64, 512 thr
// (2m x 8n warps), warp tile 64x32.  Fragment-packed smem, 3-stage, 32 chunks.
struct ProjParams {
    const __half *A[5], *B[5];
    const float* bias[5];
    float* C[5];
};

#define TSTAGEB 49152                // A 16KB + B 32KB
#define TSMEM   (3*TSTAGEB)          // 147456 -> 1 CTA/SM
#define NCHUNK  32                   // 2048 / 64

__global__ __launch_bounds__(512, 1) void proj_mma(ProjParams P)
{
    extern __shared__ __align__(128) char smem[];
    const int g  = blockIdx.z;
    const int bn = blockIdx.x * 256;
    const int bm = blockIdx.y * 128;
    const int tid  = threadIdx.x;
    const int lane = tid & 31;
    const int wid  = tid >> 5;          // 0..15
    const int wm = (wid & 1) * 64;
    const int wn = (wid >> 1) * 32;
    const int wm16 = (wid & 1) * 4;     // m-tile base (16-row tiles)
    const int wn8  = (wid >> 1) * 4;    // n-tile base (8-col tiles) 0..28
    const uint32_t sbase = smem_u32(smem);

    const __half* A = P.A[g];
    const __half* B = P.B[g];
    const float* bias = P.bias[g];
    float* C = P.C[g];

    const int T0  = blockIdx.y * 8;     // first m-tile
    const int NT0 = blockIdx.x * 32;    // first n-tile

    float acc[4][4][4];
#pragma unroll
    for (int i = 0; i < 4; i++)
#pragma unroll
        for (int j = 0; j < 4; j++)
#pragma unroll
            for (int k = 0; k < 4; k++) acc[i][j][k] = 0.f;

    // 3072 cp16 per chunk (A 1024 + B 2048) -> 6 per thread, contiguous
    auto load_chunk = [&](int c, int s) {
        const uint32_t sb = sbase + s * TSTAGEB;
#pragma unroll
        for (int u = 0; u < 6; u++) {
            int idx = u * 512 + tid;
            if (idx < 1024) {                  // A: 8 tiles x 128 cp16 (2KB ea)
                int t = idx >> 7, w = idx & 127;
                cp16(sb + t * 2048 + w * 16,
                     A + (((size_t)(T0 + t) * 32 + c) * 1024 + w * 8));
            } else {                           // B: 32 tiles x 64 cp16 (1KB ea)
                int j = idx - 1024;
                int nt = j >> 6, w = j & 63;
                cp16(sb + 16384 + nt * 1024 + w * 16,
                     B + (((size_t)(NT0 + nt) * 32 + c) * 512 + w * 8));
            }
        }
    };

    load_chunk(0, 0); CP_COMMIT();
    load_chunk(1, 1); CP_COMMIT();

    for (int it = 0; it < NCHUNK; it++) {
        const int cur = it % 3;
        if (it == NCHUNK - 1) { CP_WAIT0(); } else { CP_WAIT1(); }
        __syncthreads();
        if (it + 2 < NCHUNK) {
            load_chunk(it + 2, (it + 2) % 3);
            CP_COMMIT();
        }

        const char* sc = smem + cur * TSTAGEB;
#pragma unroll
        for (int ks = 0; ks < 4; ks++) {
            uint2 bfr[4];
#pragma unroll
            for (int nj = 0; nj < 4; nj++)
                bfr[nj] = *(const uint2*)(sc + 16384 + (wn8 + nj) * 1024 +
                                          ks * 256 + lane * 8);
#pragma unroll
            for (int mi = 0; mi < 4; mi++) {
                uint4 afr = *(const uint4*)(sc + (wm16 + mi) * 2048 +
                                            ks * 512 + lane * 16);
#pragma unroll
                for (int nj = 0; nj < 4; nj++)
                    mma16816h(acc[mi][nj], afr, bfr[nj]);
            }
        }
    }

    const int gq = lane >> 2;
    const int tq = lane & 3;
#pragma unroll
    for (int mi = 0; mi < 4; mi++) {
#pragma unroll
        for (int nj = 0; nj < 4; nj++) {
            int col = bn + wn + nj * 8 + tq * 2;
            float b0 = __ldg(bias + col);
            float b1 = __ldg(bias + col + 1);
            int row0 = bm + wm + mi * 16 + gq;
            *(float2*)(C + (size_t)row0 * HDIM + col) =
                make_float2(acc[mi][nj][0] + b0, acc[mi][nj][1] + b1);
            *(float2*)(C + (size_t)(row0 + 8) * HDIM + col) =
                make_float2(acc[mi][nj][2] + b0, acc[mi][nj][3] + b1);
        }
    }
}

// =============== qk pack: build concat fp16 hi/lo operands =================
__global__ __launch_bounds__(256) void qkpack_kernel(const float* __restrict__ param)
{
    size_t i2 = (size_t)blockIdx.x * 256 + threadIdx.x;
    if (i2 >= (size_t)BATCH * NSEQ * HDIM / 2) return;
    size_t i = i2 * 2;
    size_t bn = i / HDIM;
    int    h  = (int)(i % HDIM);
    size_t base = bn * KCAT + h;

    float2 lq = *(const float2*)(g_q1 + i);
    float2 ll = *(const float2*)(g_q2 + i);
    float2 pp = *(const float2*)(param + i);
    float2 lk = *(const float2*)(g_lk + i);
    float2 kl = *(const float2*)(g_kloc + i);

    __half h0, l0, h1, l1;
    split_f16(lq.x + pp.x, h0, l0); split_f16(lq.y + pp.y, h1, l1);
    *(__half2*)(gQc_hi + base) = __halves2half2(h0, h1);
    *(__half2*)(gQc_lo + base) = __halves2half2(l0, l1);
    split_f16(lq.x + ll.x, h0, l0); split_f16(lq.y + ll.y, h1, l1);
    *(__half2*)(gQc_hi + base + DDIM) = __halves2half2(h0, h1);
    *(__half2*)(gQc_lo + base + DDIM) = __halves2half2(l0, l1);
    split_f16(lk.x, h0, l0); split_f16(lk.y, h1, l1);
    *(__half2*)(gKc_hi + base) = __halves2half2(h0, h1);
    *(__half2*)(gKc_lo + base) = __halves2half2(l0, l1);
    split_f16(kl.x, h0, l0); split_f16(kl.y, h1, l1);
    *(__half2*)(gKc_hi + base + DDIM) = __halves2half2(h0, h1);
    *(__half2*)(gKc_lo + base + DDIM) = __halves2half2(l0, l1);
}

// =================== HMMA scores GEMM (128x128, split-K 4, fp16) ===========
#define SSTAGE 40960
#define SSMEM  (2*SSTAGE)
#define SKCH   32            // chunks per K-quarter (128/4)

__global__ __launch_bounds__(256, 2) void scores_mma()
{
    extern __shared__ __align__(128) char smem[];
    const int bz = blockIdx.z;
    const int b  = bz >> 2;
    const int kz = bz & 3;
    const int m0 = blockIdx.x * 128;
    const int n0 = blockIdx.y * 128;
    const int tid  = threadIdx.x;
    const int lane = tid & 31;
    const int wid  = tid >> 5;
    const int wm = (wid & 1) * 64;
    const int wn = (wid >> 1) * 32;
    const uint32_t sbase = smem_u32(smem);

    const size_t bo = (size_t)b * NSEQ * KCAT;
    const __half* Ahi = gQc_hi + bo;
    const __half* Alo = gQc_lo + bo;
    const __half* Bhi = gKc_hi + bo;
    const __half* Blo = gKc_lo + bo;

    float acc[4][4][4];
#pragma unroll
    for (int i = 0; i < 4; i++)
#pragma unroll
        for (int j = 0; j < 4; j++)
#pragma unroll
            for (int k = 0; k < 4; k++) acc[i][j][k] = 0.f;

    const int c0 = kz * SKCH;

    auto load_chunk = [&](int chunk, int s) {
        const int k0 = (c0 + chunk) * 32;
        const uint32_t sb = sbase + s * SSTAGE;
#pragma unroll
        for (int u = 0; u < 8; u++) {
            int idx = u * 256 + tid;
            int region = idx >> 9;
            int i2 = idx & 511;
            int r = i2 >> 2, c = i2 & 3;
            const __half* base =
                (region == 0) ? Ahi : (region == 1) ? Alo
                              : (region == 2) ? Bhi : Blo;
            int row = ((region < 2) ? n0 : m0) + r;
            if (row > NSEQ - 1) row = NSEQ - 1;
            cp16(sb + region * 10240 + r * 80 + c * 16,
                 base + (size_t)row * KCAT + k0 + c * 8);
        }
    };

    load_chunk(0, 0);
    CP_COMMIT();

    const int lrow = (lane & 7) + ((lane >> 3) & 1) * 8;
    const int lcol = (lane >> 4) * 8;

    for (int it = 0; it < SKCH; it++) {
        const int cur = it & 1;
        if (it + 1 < SKCH) {
            load_chunk(it + 1, (it + 1) & 1);
            CP_COMMIT();
            CP_WAIT1();
        } else {
            CP_WAIT0();
        }
        __syncthreads();

        const uint32_t sb = sbase + cur * SSTAGE;
#pragma unroll
        for (int ks = 0; ks < 2; ks++) {
            const int colb = (ks * 16 + lcol) * 2;
            uint32_t Bh[4][2], Bl[4][2];
#pragma unroll
            for (int half = 0; half < 2; half++) {
                const int nrow = wn + half * 16 + lrow;
                uint32_t r0, r1, r2, r3;
                ldx4(sb + 20480 + nrow * 80 + colb, r0, r1, r2, r3);
                Bh[half * 2 + 0][0] = r0; Bh[half * 2 + 1][0] = r1;
                Bh[half * 2 + 0][1] = r2; Bh[half * 2 + 1][1] = r3;
                ldx4(sb + 30720 + nrow * 80 + colb, r0, r1, r2, r3);
                Bl[half * 2 + 0][0] = r0; Bl[half * 2 + 1][0] = r1;
                Bl[half * 2 + 0][1] = r2; Bl[half * 2 + 1][1] = r3;
            }
#pragma unroll
            for (int p = 0; p < 2; p++) {
                uint32_t ah[2][4], al[2][4];
#pragma unroll
                for (int m2 = 0; m2 < 2; m2++) {
                    const int mrow = wm + (p * 2 + m2) * 16 + lrow;
                    ldx4(sb + mrow * 80 + colb,
                         ah[m2][0], ah[m2][1], ah[m2][2], ah[m2][3]);
                    ldx4(sb + 10240 + mrow * 80 + colb,
                         al[m2][0], al[m2][1], al[m2][2], al[m2][3]);
                }
#pragma unroll
                for (int m2 = 0; m2 < 2; m2++)
#pragma unroll
                    for (int nj = 0; nj < 4; nj++)
                        mma16816(acc[p * 2 + m2][nj], ah[m2], Bh[nj]);
#pragma unroll
                for (int m2 = 0; m2 < 2; m2++)
#pragma unroll
                    for (int nj = 0; nj < 4; nj++)
                        mma16816(acc[p * 2 + m2][nj], ah[m2], Bl[nj]);
#pragma unroll
                for (int m2 = 0; m2 < 2; m2++)
#pragma unroll
                    for (int nj = 0; nj < 4; nj++)
                        mma16816(acc[p * 2 + m2][nj], al[m2], Bh[nj]);
            }
        }
        __syncthreads();
    }

    float* sc = g_scoresP + (size_t)kz * BNN + (size_t)b * NSEQ * NSEQ;
    const int gq = lane >> 2;
    const int tq = lane & 3;
#pragma unroll
    for (int mi = 0; mi < 4; mi++) {
#pragma unroll
        for (int nj = 0; nj < 4; nj++) {
            int col = m0 + wn + nj * 8 + tq * 2;
            if (col >= NSEQ) continue;
            int row0 = n0 + wm + mi * 16 + gq;
            if (row0 < NSEQ)
                *(float2*)(sc + (size_t)row0 * NSEQ + col) =
                    make_float2(acc[mi][nj][0], acc[mi][nj][1]);
            int row1 = row0 + 8;
            if (row1 < NSEQ)
                *(float2*)(sc + (size_t)row1 * NSEQ + col) =
                    make_float2(acc[mi][nj][2], acc[mi][nj][3]);
        }
    }
}

// -------- softmax: sum 4 split-K partials -> fp16 hi/lo attn (pad 224) ----
__global__ __launch_bounds__(256) void softmax_kernel()
{
    const int row = blockIdx.x;
    const size_t off = (size_t)row * NSEQ;
    const int tid = threadIdx.x;
    __shared__ float red[8];

    float sval = -3.0e38f;
    if (tid < NSEQ) {
        sval = g_scoresP[off + tid] + g_scoresP[BNN + off + tid]
             + g_scoresP[2 * (size_t)BNN + off + tid]
             + g_scoresP[3 * (size_t)BNN + off + tid];
    }
    float v = sval;
#pragma unroll
    for (int o = 16; o; o >>= 1) v = fmaxf(v, __shfl_xor_sync(0xffffffffu, v, o));
    if ((tid & 31) == 0) red[tid >> 5] = v;
    __syncthreads();
    float vmax = red[0];
#pragma unroll
    for (int w = 1; w < 8; w++) vmax = fmaxf(vmax, red[w]);

    const float scale = 0.02209708691207961f;  // 1/sqrt(2048)
    float e = (tid < NSEQ) ? __expf((sval - vmax) * scale) : 0.f;
    float sum = e;
#pragma unroll
    for (int o = 16; o; o >>= 1) sum += __shfl_xor_sync(0xffffffffu, sum, o);
    __syncthreads();
    if ((tid & 31) == 0) red[tid >> 5] = sum;
    __syncthreads();
    float tot = 0.f;
#pragma unroll
    for (int w = 0; w < 8; w++) tot += red[w];

    if (tid < KOUT) {
        float a = (tid < NSEQ) ? e / tot : 0.f;
        __half h, l;
        split_f16(a, h, l);
        gAttn_hi[(size_t)row * KOUT + tid] = h;
        gAttn_lo[(size_t)row * KOUT + tid] = l;
    }
}

// ---------------- lv transpose + split: lvT[b][o][m] ----------------------
__global__ __launch_bounds__(256) void lvT_kernel()
{
    __shared__ float t[32][33];
    const int b  = blockIdx.z;
    const int o0 = blockIdx.x * 32;
    const int m0 = blockIdx.y * 32;
    const int tx = threadIdx.x, ty = threadIdx.y;
    const float* lv = g_lv + (size_t)b * NSEQ * HDIM;
#pragma unroll
    for (int r = ty; r < 32; r += 8) {
        int m = m0 + r;
        t[r][tx] = (m < NSEQ) ? lv[(size_t)m * HDIM + o0 + tx] : 0.f;
    }
    __syncthreads();
#pragma unroll
    for (int r = ty; r < 32; r += 8) {
        __half h, l;
        split_f16(t[tx][r], h, l);
        size_t off = ((size_t)b * HDIM + o0 + r) * KOUT + m0 + tx;
        gLvT_hi[off] = h;
        gLvT_lo[off] = l;
    }
}

// =================== HMMA output GEMM (fp16) ===============================
#define ONCHUNK 7

__global__ __launch_bounds__(256, 2) void out_mma(float* __restrict__ out)
{
    extern __shared__ __align__(128) char smem[];
    const int b  = blockIdx.z;
    const int o0 = blockIdx.x * 128;
    const int n0 = blockIdx.y * 128;
    const int tid  = threadIdx.x;
    const int lane = tid & 31;
    const int wid  = tid >> 5;
    const int wm = (wid & 1) * 64;
    const int wn = (wid >> 1) * 32;
    const uint32_t sbase = smem_u32(smem);

    const __half* Ahi = gAttn_hi + (size_t)b * NSEQ * KOUT;
    const __half* Alo = gAttn_lo + (size_t)b * NSEQ * KOUT;
    const __half* Bhi = gLvT_hi + (size_t)b * HDIM * KOUT;
    const __half* Blo = gLvT_lo + (size_t)b * HDIM * KOUT;

    float acc[4][4][4];
#pragma unroll
    for (int i = 0; i < 4; i++)
#pragma unroll
        for (int j = 0; j < 4; j++)
#pragma unroll
            for (int k = 0; k < 4; k++) acc[i][j][k] = 0.f;

    auto load_chunk = [&](int chunk, int s) {
        const int k0 = chunk * 32;
        const uint32_t sb = sbase + s * SSTAGE;
#pragma unroll
        for (int u = 0; u < 8; u++) {
            int idx = u * 256 + tid;
            int region = idx >> 9;
            int i2 = idx & 511;
            int r = i2 >> 2, c = i2 & 3;
            const __half* base;
            size_t off;
            if (region < 2) {
                int row = n0 + r; if (row > NSEQ - 1) row = NSEQ - 1;
                base = region ? Alo : Ahi;
                off = (size_t)row * KOUT + k0 + c * 8;
            } else {
                base = (region == 3) ? Blo : Bhi;
                off = (size_t)(o0 + r) * KOUT + k0 + c * 8;
            }
            cp16(sb + region * 10240 + r * 80 + c * 16, base + off);
        }
    };

    load_chunk(0, 0);
    CP_COMMIT();

    const int lrow = (lane & 7) + ((lane >> 3) & 1) * 8;
    const int lcol = (lane >> 4) * 8;

    for (int it = 0; it < ONCHUNK; it++) {
        const int cur = it & 1;
        if (it + 1 < ONCHUNK) {
            load_chunk(it + 1, (it + 1) & 1);
            CP_COMMIT();
            CP_WAIT1();
        } else {
            CP_WAIT0();
        }
        __syncthreads();

        const uint32_t sb = sbase + cur * SSTAGE;
#pragma unroll
        for (int ks = 0; ks < 2; ks++) {
            const int colb = (ks * 16 + lcol) * 2;
            uint32_t Bh[4][2], Bl[4][2];
#pragma unroll
            for (int half = 0; half < 2; half++) {
                const int nrow = wn + half * 16 + lrow;
                uint32_t r0, r1, r2, r3;
                ldx4(sb + 20480 + nrow * 80 + colb, r0, r1, r2, r3);
                Bh[half * 2 + 0][0] = r0; Bh[half * 2 + 1][0] = r1;
                Bh[half * 2 + 0][1] = r2; Bh[half * 2 + 1][1] = r3;
                ldx4(sb + 30720 + nrow * 80 + colb, r0, r1, r2, r3);
                Bl[half * 2 + 0][0] = r0; Bl[half * 2 + 1][0] = r1;
                Bl[half * 2 + 0][1] = r2; Bl[half * 2 + 1][1] = r3;
            }
#pragma unroll
            for (int p = 0; p < 2; p++) {
                uint32_t ah[2][4], al[2][4];
#pragma unroll
                for (int m2 = 0; m2 < 2; m2++) {
                    const int mrow = wm + (p * 2 + m2) * 16 + lrow;
                    ldx4(sb + mrow * 80 + colb,
                         ah[m2][0], ah[m2][1], ah[m2][2], ah[m2][3]);
                    ldx4(sb + 10240 + mrow * 80 + colb,
                         al[m2][0], al[m2][1], al[m2][2], al[m2][3]);
                }
#pragma unroll
                for (int m2 = 0; m2 < 2; m2++)
#pragma unroll
                    for (int nj = 0; nj < 4; nj++)
                        mma16816(acc[p * 2 + m2][nj], ah[m2], Bh[nj]);
#pragma unroll
                for (int m2 = 0; m2 < 2; m2++)
#pragma unroll
                    for (int nj = 0; nj < 4; nj++)
                        mma16816(acc[p * 2 + m2][nj], ah[m2], Bl[nj]);
#pragma unroll
                for (int m2 = 0; m2 < 2; m2++)
#pragma unroll
                    for (int nj = 0; nj < 4; nj++)
                        mma16816(acc[p * 2 + m2][nj], al[m2], Bh[nj]);
            }
        }
        __syncthreads();
    }

    const int gq = lane >> 2;
    const int tq = lane & 3;
#pragma unroll
    for (int mi = 0; mi < 4; mi++) {
#pragma unroll
        for (int nj = 0; nj < 4; nj++) {
            int col = o0 + wn + nj * 8 + tq * 2;
            int row0 = n0 + wm + mi * 16 + gq;
            if (row0 < NSEQ)
                *(float2*)(out + ((size_t)b * NSEQ + row0) * HDIM + col) =
                    make_float2(acc[mi][nj][0], acc[mi][nj][1]);
            int row1 = row0 + 8;
            if (row1 < NSEQ)
                *(float2*)(out + ((size_t)b * NSEQ + row1) * HDIM + col) =
                    make_float2(acc[mi][nj][2], acc[mi][nj][3]);
        }
    }
}

// ---------------------------------------------------------------------------
extern "C" void kernel_launch(void* const* d_in, const int* in_sizes, int n_in,
                              void* d_out, int out_size)
{
    const float* input_query = (const float*)d_in[0];
    const float* input_key   = (const float*)d_in[1];
    const float* input_value = (const float*)d_in[2];
    const float* loc_vector  = (const float*)d_in[3];
    const float* Wq   = (const float*)d_in[4];
    const float* bq   = (const float*)d_in[5];
    const float* Wk   = (const float*)d_in[6];
    const float* bk   = (const float*)d_in[7];
    const float* Wv   = (const float*)d_in[8];
    const float* bv   = (const float*)d_in[9];
    const float* Wloc = (const float*)d_in[10];
    const float* bloc = (const float*)d_in[11];
    const float* Wlk  = (const float*)d_in[12];
    const float* blk  = (const float*)d_in[13];
    const float* param = (const float*)d_in[14];
    float* out = (float*)d_out;

    float *q1, *q2, *lk, *kloc, *lv;
    __half *Ah, *Wh;
    cudaGetSymbolAddress((void**)&q1,   g_q1);
    cudaGetSymbolAddress((void**)&q2,   g_q2);
    cudaGetSymbolAddress((void**)&lk,   g_lk);
    cudaGetSymbolAddress((void**)&kloc, g_kloc);
    cudaGetSymbolAddress((void**)&lv,   g_lv);
    cudaGetSymbolAddress((void**)&Ah,   gAh);
    cudaGetSymbolAddress((void**)&Wh,   gWh);

    cudaFuncSetAttribute(proj_mma, cudaFuncAttributeMaxDynamicSharedMemorySize,
                         TSMEM);
    cudaFuncSetAttribute(scores_mma, cudaFuncAttributeMaxDynamicSharedMemorySize,
                         SSMEM);
    cudaFuncSetAttribute(out_mma, cudaFuncAttributeMaxDynamicSharedMemorySize,
                         SSMEM);

    ConvAP CA;
    CA.src[0] = input_query; CA.src[1] = input_key;
    CA.src[2] = input_value; CA.src[3] = loc_vector;
    convA_kernel<<<dim3(200, 16, 4), 256>>>(CA);

    ConvWP CW;
    CW.src[0] = Wq; CW.src[1] = Wloc; CW.src[2] = Wk; CW.src[3] = Wlk; CW.src[4] = Wv;
    convW_kernel<<<dim3(256, 16, 5), 256>>>(CW);

    ProjParams P;
    const int aidx[5] = {0, 3, 1, 3, 2};     // query, loc, key, loc, value
    const float* biases[5] = {bq, bloc, bk, blk, bv};
    float* outs[5] = {q1, q2, lk, kloc, lv};
    for (int g = 0; g < 5; g++) {
        P.A[g]    = Ah + (size_t)aidx[g] * MK;
        P.B[g]    = Wh + (size_t)g * KN;
        P.bias[g] = biases[g];
        P.C[g]    = outs[g];
    }
    proj_mma<<<dim3(HDIM / 256, MTOT / 128, 5), 512, TSMEM>>>(P);

    qkpack_kernel<<<(BATCH * NSEQ * HDIM / 2 + 255) / 256, 256>>>(param);
    lvT_kernel<<<dim3(HDIM / 32, KOUT / 32, BATCH), dim3(32, 8)>>>();

    scores_mma<<<dim3(2, 2, BATCH * 4), 256, SSMEM>>>();
    softmax_kernel<<<BATCH * NSEQ, 256>>>();
    out_mma<<<dim3(HDIM / 128, 2, BATCH), 256, SSMEM>>>(out);
}

// round 15
// speedup vs baseline: 1.0751x; 1.0751x over previous
#include <cuda_runtime.h>
#include <cuda_bf16.h>
#include <cuda_fp16.h>
#include <math.h>
#include <stdint.h>

#define BATCH 16
#define NSEQ  200
#define DDIM  2048
#define HDIM  2048
#define MTOT  (BATCH*NSEQ)          // 3200
#define MK    (MTOT*DDIM)
#define KN    (DDIM*HDIM)
#define KCAT  4096                  // scores concatenated K
#define KOUT  224                   // out GEMM K (200 padded)
#define BNN   (BATCH*NSEQ*NSEQ)

// ---------------- scratch (device globals) ---------------------------------
__device__ float g_q1[BATCH*NSEQ*HDIM];
__device__ float g_q2[BATCH*NSEQ*HDIM];
__device__ float g_lk[BATCH*NSEQ*HDIM];
__device__ float g_kloc[BATCH*NSEQ*HDIM];
__device__ float g_lv[BATCH*NSEQ*HDIM];
__device__ float g_scoresP[4*BNN];      // split-K partial scores

// fragment-packed fp16 operands for projections.
__device__ __align__(16) __half gAh[4*MK];
__device__ __align__(16) __half gWh[5*KN];

// scores/out fp16 hi/lo split operands
__device__ __align__(16) __half gQc_hi[BATCH*NSEQ*KCAT];
__device__ __align__(16) __half gQc_lo[BATCH*NSEQ*KCAT];
__device__ __align__(16) __half gKc_hi[BATCH*NSEQ*KCAT];
__device__ __align__(16) __half gKc_lo[BATCH*NSEQ*KCAT];
__device__ __align__(16) __half gAttn_hi[BATCH*NSEQ*KOUT];
__device__ __align__(16) __half gAttn_lo[BATCH*NSEQ*KOUT];
__device__ __align__(16) __half gLvT_hi[BATCH*HDIM*KOUT];
__device__ __align__(16) __half gLvT_lo[BATCH*HDIM*KOUT];

// ============================ helpers ======================================
__device__ __forceinline__ uint32_t smem_u32(const void* p) {
    uint32_t a;
    asm("{ .reg .u64 t; cvta.to.shared.u64 t, %1; cvt.u32.u64 %0, t; }"
        : "=r"(a) : "l"(p));
    return a;
}
__device__ __forceinline__ void cp16(uint32_t dst, const void* src) {
    asm volatile("cp.async.cg.shared.global [%0], [%1], 16;" :: "r"(dst), "l"(src));
}
#define CP_COMMIT() asm volatile("cp.async.commit_group;" ::: "memory")
#define CP_WAIT1()  asm volatile("cp.async.wait_group 1;" ::: "memory")
#define CP_WAIT0()  asm volatile("cp.async.wait_group 0;" ::: "memory")

__device__ __forceinline__ void ldx4(uint32_t addr, uint32_t& r0, uint32_t& r1,
                                     uint32_t& r2, uint32_t& r3) {
    asm volatile("ldmatrix.sync.aligned.m8n8.x4.shared.b16 {%0,%1,%2,%3}, [%4];"
                 : "=r"(r0), "=r"(r1), "=r"(r2), "=r"(r3) : "r"(addr));
}
// fp16 m16n8k16 (array-operand form, used by scores/out)
__device__ __forceinline__ void mma16816(float* c, const uint32_t* a,
                                         const uint32_t* b) {
    asm volatile(
        "mma.sync.aligned.m16n8k16.row.col.f32.f16.f16.f32 "
        "{%0,%1,%2,%3}, {%4,%5,%6,%7}, {%8,%9}, {%0,%1,%2,%3};"
        : "+f"(c[0]), "+f"(c[1]), "+f"(c[2]), "+f"(c[3])
        : "r"(a[0]), "r"(a[1]), "r"(a[2]), "r"(a[3]), "r"(b[0]), "r"(b[1]));
}
// fp16 m16n8k16 (vector-operand form, used by proj)
__device__ __forceinline__ void mma16816h(float* c, const uint4 a,
                                          const uint2 b) {
    asm volatile(
        "mma.sync.aligned.m16n8k16.row.col.f32.f16.f16.f32 "
        "{%0,%1,%2,%3}, {%4,%5,%6,%7}, {%8,%9}, {%0,%1,%2,%3};"
        : "+f"(c[0]), "+f"(c[1]), "+f"(c[2]), "+f"(c[3])
        : "r"(a.x), "r"(a.y), "r"(a.z), "r"(a.w), "r"(b.x), "r"(b.y));
}
__device__ __forceinline__ void split_f16(float x, __half& h, __half& l) {
    h = __float2half_rn(x);
    l = __float2half_rn(x - __half2float(h));
}

// =================== conversion kernels (fp16 fragment packing) ============
struct ConvAP { const float* src[4]; };
__global__ __launch_bounds__(256) void convA_kernel(ConvAP P)
{
    const int mat = blockIdx.z;
    const int T   = blockIdx.x;
    const int t   = threadIdx.x;
    const int c   = blockIdx.y * 2 + (t >> 7);     // chunk (K=64)
    const int g   = t & 127;
    const int ks  = g >> 5;                        // k-step (K=16)
    const int lane = g & 31;
    const int gq = lane >> 2, tq = lane & 3;
    const float* src = P.src[mat];

    const size_t r0 = (size_t)(T * 16 + gq) * DDIM;
    const size_t r8 = r0 + 8 * DDIM;
    const int k0 = c * 64 + ks * 16 + tq * 2;

    __half2 h0 = __floats2half2_rn(src[r0 + k0],     src[r0 + k0 + 1]);
    __half2 h1 = __floats2half2_rn(src[r8 + k0],     src[r8 + k0 + 1]);
    __half2 h2 = __floats2half2_rn(src[r0 + k0 + 8], src[r0 + k0 + 9]);
    __half2 h3 = __floats2half2_rn(src[r8 + k0 + 8], src[r8 + k0 + 9]);
    uint4 v;
    v.x = *(uint32_t*)&h0; v.y = *(uint32_t*)&h1;
    v.z = *(uint32_t*)&h2; v.w = *(uint32_t*)&h3;

    *(uint4*)(gAh + (size_t)mat * MK +
              (((size_t)(T * 32 + c) * 4 + ks) * 256 + lane * 8)) = v;
}

struct ConvWP { const float* src[5]; };
__global__ __launch_bounds__(256) void convW_kernel(ConvWP P)
{
    const int w  = blockIdx.z;
    const int T8 = blockIdx.x;
    const int t  = threadIdx.x;
    const int c  = blockIdx.y * 2 + (t >> 7);
    const int g  = t & 127;
    const int ks = g >> 5;
    const int lane = g & 31;
    const int gq = lane >> 2, tq = lane & 3;
    const float* W = P.src[w];

    const int n  = T8 * 8 + gq;
    const int k0 = c * 64 + ks * 16 + tq * 2;
    __half2 b0 = __floats2half2_rn(W[(size_t)k0 * HDIM + n],
                                   W[(size_t)(k0 + 1) * HDIM + n]);
    __half2 b1 = __floats2half2_rn(W[(size_t)(k0 + 8) * HDIM + n],
                                   W[(size_t)(k0 + 9) * HDIM + n]);
    uint2 v;
    v.x = *(uint32_t*)&b0; v.y = *(uint32_t*)&b1;
    *(uint2*)(gWh + (size_t)w * KN +
              (((size_t)(T8 * 32 + c) * 4 + ks) * 128 + lane * 4)) = v;
}

// =================== FP16 projection GEMM ==================================
// C[3200,2048] = A @ Wt^T + bias.  BM=128 x BN=128, K-chunk 64, 128 thr
// (2m x 2n warps), warp tile 64x64.  Minimal inter-warp fragment redundancy
// (A-red 2, B-red 2 -> 64KB LDS/chunk).  3-stage, 2 CTAs/SM.
struct ProjParams {
    const __half *A[5], *B[5];
    const float* bias[5];
    float* C[5];
};

#define TSTAGEB 32768                // A 16KB + B 16KB
#define TSMEM   (3*TSTAGEB)          // 98304 -> 2 CTAs/SM
#define NCHUNK  32                   // 2048 / 64

__global__ __launch_bounds__(128, 2) void proj_mma(ProjParams P)
{
    extern __shared__ __align__(128) char smem[];
    const int g  = blockIdx.z;
    const int bn = blockIdx.x * 128;
    const int bm = blockIdx.y * 128;
    const int tid  = threadIdx.x;
    const int lane = tid & 31;
    const int wid  = tid >> 5;          // 0..3
    const int wm = (wid & 1) * 64;
    const int wn = (wid >> 1) * 64;
    const int wm16 = (wid & 1) * 4;     // m-tile base (16-row tiles)
    const int wn8  = (wid >> 1) * 8;    // n-tile base (8-col tiles)
    const uint32_t sbase = smem_u32(smem);

    const __half* A = P.A[g];
    const __half* B = P.B[g];
    const float* bias = P.bias[g];
    float* C = P.C[g];

    const int T0  = blockIdx.y * 8;     // first m-tile
    const int NT0 = blockIdx.x * 16;    // first n-tile

    float acc[4][8][4];
#pragma unroll
    for (int i = 0; i < 4; i++)
#pragma unroll
        for (int j = 0; j < 8; j++)
#pragma unroll
            for (int k = 0; k < 4; k++) acc[i][j][k] = 0.f;

    // 2048 cp16 per chunk (A 1024 + B 1024) -> 16 per thread, contiguous
    auto load_chunk = [&](int c, int s) {
        const uint32_t sb = sbase + s * TSTAGEB;
#pragma unroll
        for (int u = 0; u < 16; u++) {
            int idx = u * 128 + tid;
            if (idx < 1024) {                  // A: 8 tiles x 128 cp16 (2KB ea)
                int t = idx >> 7, w = idx & 127;
                cp16(sb + t * 2048 + w * 16,
                     A + (((size_t)(T0 + t) * 32 + c) * 1024 + w * 8));
            } else {                           // B: 16 tiles x 64 cp16 (1KB ea)
                int j = idx - 1024;
                int nt = j >> 6, w = j & 63;
                cp16(sb + 16384 + nt * 1024 + w * 16,
                     B + (((size_t)(NT0 + nt) * 32 + c) * 512 + w * 8));
            }
        }
    };

    load_chunk(0, 0); CP_COMMIT();
    load_chunk(1, 1); CP_COMMIT();

    for (int it = 0; it < NCHUNK; it++) {
        const int cur = it % 3;
        if (it == NCHUNK - 1) { CP_WAIT0(); } else { CP_WAIT1(); }
        __syncthreads();
        if (it + 2 < NCHUNK) {
            load_chunk(it + 2, (it + 2) % 3);
            CP_COMMIT();
        }

        const char* sc = smem + cur * TSTAGEB;
#pragma unroll
        for (int ks = 0; ks < 4; ks++) {
            uint2 bfr[8];
#pragma unroll
            for (int nj = 0; nj < 8; nj++)
                bfr[nj] = *(const uint2*)(sc + 16384 + (wn8 + nj) * 1024 +
                                          ks * 256 + lane * 8);
#pragma unroll
            for (int mi = 0; mi < 4; mi++) {
                uint4 afr = *(const uint4*)(sc + (wm16 + mi) * 2048 +
                                            ks * 512 + lane * 16);
#pragma unroll
                for (int nj = 0; nj < 8; nj++)
                    mma16816h(acc[mi][nj], afr, bfr[nj]);
            }
        }
    }

    const int gq = lane >> 2;
    const int tq = lane & 3;
#pragma unroll
    for (int mi = 0; mi < 4; mi++) {
#pragma unroll
        for (int nj = 0; nj < 8; nj++) {
            int col = bn + wn + nj * 8 + tq * 2;
            float b0 = __ldg(bias + col);
            float b1 = __ldg(bias + col + 1);
            int row0 = bm + wm + mi * 16 + gq;
            *(float2*)(C + (size_t)row0 * HDIM + col) =
                make_float2(acc[mi][nj][0] + b0, acc[mi][nj][1] + b1);
            *(float2*)(C + (size_t)(row0 + 8) * HDIM + col) =
                make_float2(acc[mi][nj][2] + b0, acc[mi][nj][3] + b1);
        }
    }
}

// =============== qk pack: build concat fp16 hi/lo operands =================
__global__ __launch_bounds__(256) void qkpack_kernel(const float* __restrict__ param)
{
    size_t i2 = (size_t)blockIdx.x * 256 + threadIdx.x;
    if (i2 >= (size_t)BATCH * NSEQ * HDIM / 2) return;
    size_t i = i2 * 2;
    size_t bn = i / HDIM;
    int    h  = (int)(i % HDIM);
    size_t base = bn * KCAT + h;

    float2 lq = *(const float2*)(g_q1 + i);
    float2 ll = *(const float2*)(g_q2 + i);
    float2 pp = *(const float2*)(param + i);
    float2 lk = *(const float2*)(g_lk + i);
    float2 kl = *(const float2*)(g_kloc + i);

    __half h0, l0, h1, l1;
    split_f16(lq.x + pp.x, h0, l0); split_f16(lq.y + pp.y, h1, l1);
    *(__half2*)(gQc_hi + base) = __halves2half2(h0, h1);
    *(__half2*)(gQc_lo + base) = __halves2half2(l0, l1);
    split_f16(lq.x + ll.x, h0, l0); split_f16(lq.y + ll.y, h1, l1);
    *(__half2*)(gQc_hi + base + DDIM) = __halves2half2(h0, h1);
    *(__half2*)(gQc_lo + base + DDIM) = __halves2half2(l0, l1);
    split_f16(lk.x, h0, l0); split_f16(lk.y, h1, l1);
    *(__half2*)(gKc_hi + base) = __halves2half2(h0, h1);
    *(__half2*)(gKc_lo + base) = __halves2half2(l0, l1);
    split_f16(kl.x, h0, l0); split_f16(kl.y, h1, l1);
    *(__half2*)(gKc_hi + base + DDIM) = __halves2half2(h0, h1);
    *(__half2*)(gKc_lo + base + DDIM) = __halves2half2(l0, l1);
}

// =================== HMMA scores GEMM (128x128, split-K 4, fp16) ===========
#define SSTAGE 40960
#define SSMEM  (2*SSTAGE)
#define SKCH   32            // chunks per K-quarter (128/4)

__global__ __launch_bounds__(256, 2) void scores_mma()
{
    extern __shared__ __align__(128) char smem[];
    const int bz = blockIdx.z;
    const int b  = bz >> 2;
    const int kz = bz & 3;
    const int m0 = blockIdx.x * 128;
    const int n0 = blockIdx.y * 128;
    const int tid  = threadIdx.x;
    const int lane = tid & 31;
    const int wid  = tid >> 5;
    const int wm = (wid & 1) * 64;
    const int wn = (wid >> 1) * 32;
    const uint32_t sbase = smem_u32(smem);

    const size_t bo = (size_t)b * NSEQ * KCAT;
    const __half* Ahi = gQc_hi + bo;
    const __half* Alo = gQc_lo + bo;
    const __half* Bhi = gKc_hi + bo;
    const __half* Blo = gKc_lo + bo;

    float acc[4][4][4];
#pragma unroll
    for (int i = 0; i < 4; i++)
#pragma unroll
        for (int j = 0; j < 4; j++)
#pragma unroll
            for (int k = 0; k < 4; k++) acc[i][j][k] = 0.f;

    const int c0 = kz * SKCH;

    auto load_chunk = [&](int chunk, int s) {
        const int k0 = (c0 + chunk) * 32;
        const uint32_t sb = sbase + s * SSTAGE;
#pragma unroll
        for (int u = 0; u < 8; u++) {
            int idx = u * 256 + tid;
            int region = idx >> 9;
            int i2 = idx & 511;
            int r = i2 >> 2, c = i2 & 3;
            const __half* base =
                (region == 0) ? Ahi : (region == 1) ? Alo
                              : (region == 2) ? Bhi : Blo;
            int row = ((region < 2) ? n0 : m0) + r;
            if (row > NSEQ - 1) row = NSEQ - 1;
            cp16(sb + region * 10240 + r * 80 + c * 16,
                 base + (size_t)row * KCAT + k0 + c * 8);
        }
    };

    load_chunk(0, 0);
    CP_COMMIT();

    const int lrow = (lane & 7) + ((lane >> 3) & 1) * 8;
    const int lcol = (lane >> 4) * 8;

    for (int it = 0; it < SKCH; it++) {
        const int cur = it & 1;
        if (it + 1 < SKCH) {
            load_chunk(it + 1, (it + 1) & 1);
            CP_COMMIT();
            CP_WAIT1();
        } else {
            CP_WAIT0();
        }
        __syncthreads();

        const uint32_t sb = sbase + cur * SSTAGE;
#pragma unroll
        for (int ks = 0; ks < 2; ks++) {
            const int colb = (ks * 16 + lcol) * 2;
            uint32_t Bh[4][2], Bl[4][2];
#pragma unroll
            for (int half = 0; half < 2; half++) {
                const int nrow = wn + half * 16 + lrow;
                uint32_t r0, r1, r2, r3;
                ldx4(sb + 20480 + nrow * 80 + colb, r0, r1, r2, r3);
                Bh[half * 2 + 0][0] = r0; Bh[half * 2 + 1][0] = r1;
                Bh[half * 2 + 0][1] = r2; Bh[half * 2 + 1][1] = r3;
                ldx4(sb + 30720 + nrow * 80 + colb, r0, r1, r2, r3);
                Bl[half * 2 + 0][0] = r0; Bl[half * 2 + 1][0] = r1;
                Bl[half * 2 + 0][1] = r2; Bl[half * 2 + 1][1] = r3;
            }
#pragma unroll
            for (int p = 0; p < 2; p++) {
                uint32_t ah[2][4], al[2][4];
#pragma unroll
                for (int m2 = 0; m2 < 2; m2++) {
                    const int mrow = wm + (p * 2 + m2) * 16 + lrow;
                    ldx4(sb + mrow * 80 + colb,
                         ah[m2][0], ah[m2][1], ah[m2][2], ah[m2][3]);
                    ldx4(sb + 10240 + mrow * 80 + colb,
                         al[m2][0], al[m2][1], al[m2][2], al[m2][3]);
                }
#pragma unroll
                for (int m2 = 0; m2 < 2; m2++)
#pragma unroll
                    for (int nj = 0; nj < 4; nj++)
                        mma16816(acc[p * 2 + m2][nj], ah[m2], Bh[nj]);
#pragma unroll
                for (int m2 = 0; m2 < 2; m2++)
#pragma unroll
                    for (int nj = 0; nj < 4; nj++)
                        mma16816(acc[p * 2 + m2][nj], ah[m2], Bl[nj]);
#pragma unroll
                for (int m2 = 0; m2 < 2; m2++)
#pragma unroll
                    for (int nj = 0; nj < 4; nj++)
                        mma16816(acc[p * 2 + m2][nj], al[m2], Bh[nj]);
            }
        }
        __syncthreads();
    }

    float* sc = g_scoresP + (size_t)kz * BNN + (size_t)b * NSEQ * NSEQ;
    const int gq = lane >> 2;
    const int tq = lane & 3;
#pragma unroll
    for (int mi = 0; mi < 4; mi++) {
#pragma unroll
        for (int nj = 0; nj < 4; nj++) {
            int col = m0 + wn + nj * 8 + tq * 2;
            if (col >= NSEQ) continue;
            int row0 = n0 + wm + mi * 16 + gq;
            if (row0 < NSEQ)
                *(float2*)(sc + (size_t)row0 * NSEQ + col) =
                    make_float2(acc[mi][nj][0], acc[mi][nj][1]);
            int row1 = row0 + 8;
            if (row1 < NSEQ)
                *(float2*)(sc + (size_t)row1 * NSEQ + col) =
                    make_float2(acc[mi][nj][2], acc[mi][nj][3]);
        }
    }
}

// -------- softmax: sum 4 split-K partials -> fp16 hi/lo attn (pad 224) ----
__global__ __launch_bounds__(256) void softmax_kernel()
{
    const int row = blockIdx.x;
    const size_t off = (size_t)row * NSEQ;
    const int tid = threadIdx.x;
    __shared__ float red[8];

    float sval = -3.0e38f;
    if (tid < NSEQ) {
        sval = g_scoresP[off + tid] + g_scoresP[BNN + off + tid]
             + g_scoresP[2 * (size_t)BNN + off + tid]
             + g_scoresP[3 * (size_t)BNN + off + tid];
    }
    float v = sval;
#pragma unroll
    for (int o = 16; o; o >>= 1) v = fmaxf(v, __shfl_xor_sync(0xffffffffu, v, o));
    if ((tid & 31) == 0) red[tid >> 5] = v;
    __syncthreads();
    float vmax = red[0];
#pragma unroll
    for (int w = 1; w < 8; w++) vmax = fmaxf(vmax, red[w]);

    const float scale = 0.02209708691207961f;  // 1/sqrt(2048)
    float e = (tid < NSEQ) ? __expf((sval - vmax) * scale) : 0.f;
    float sum = e;
#pragma unroll
    for (int o = 16; o; o >>= 1) sum += __shfl_xor_sync(0xffffffffu, sum, o);
    __syncthreads();
    if ((tid & 31) == 0) red[tid >> 5] = sum;
    __syncthreads();
    float tot = 0.f;
#pragma unroll
    for (int w = 0; w < 8; w++) tot += red[w];

    if (tid < KOUT) {
        float a = (tid < NSEQ) ? e / tot : 0.f;
        __half h, l;
        split_f16(a, h, l);
        gAttn_hi[(size_t)row * KOUT + tid] = h;
        gAttn_lo[(size_t)row * KOUT + tid] = l;
    }
}

// ---------------- lv transpose + split: lvT[b][o][m] ----------------------
__global__ __launch_bounds__(256) void lvT_kernel()
{
    __shared__ float t[32][33];
    const int b  = blockIdx.z;
    const int o0 = blockIdx.x * 32;
    const int m0 = blockIdx.y * 32;
    const int tx = threadIdx.x, ty = threadIdx.y;
    const float* lv = g_lv + (size_t)b * NSEQ * HDIM;
#pragma unroll
    for (int r = ty; r < 32; r += 8) {
        int m = m0 + r;
        t[r][tx] = (m < NSEQ) ? lv[(size_t)m * HDIM + o0 + tx] : 0.f;
    }
    __syncthreads();
#pragma unroll
    for (int r = ty; r < 32; r += 8) {
        __half h, l;
        split_f16(t[tx][r], h, l);
        size_t off = ((size_t)b * HDIM + o0 + r) * KOUT + m0 + tx;
        gLvT_hi[off] = h;
        gLvT_lo[off] = l;
    }
}

// =================== HMMA output GEMM (fp16) ===============================
#define ONCHUNK 7

__global__ __launch_bounds__(256, 2) void out_mma(float* __restrict__ out)
{
    extern __shared__ __align__(128) char smem[];
    const int b  = blockIdx.z;
    const int o0 = blockIdx.x * 128;
    const int n0 = blockIdx.y * 128;
    const int tid  = threadIdx.x;
    const int lane = tid & 31;
    const int wid  = tid >> 5;
    const int wm = (wid & 1) * 64;
    const int wn = (wid >> 1) * 32;
    const uint32_t sbase = smem_u32(smem);

    const __half* Ahi = gAttn_hi + (size_t)b * NSEQ * KOUT;
    const __half* Alo = gAttn_lo + (size_t)b * NSEQ * KOUT;
    const __half* Bhi = gLvT_hi + (size_t)b * HDIM * KOUT;
    const __half* Blo = gLvT_lo + (size_t)b * HDIM * KOUT;

    float acc[4][4][4];
#pragma unroll
    for (int i = 0; i < 4; i++)
#pragma unroll
        for (int j = 0; j < 4; j++)
#pragma unroll
            for (int k = 0; k < 4; k++) acc[i][j][k] = 0.f;

    auto load_chunk = [&](int chunk, int s) {
        const int k0 = chunk * 32;
        const uint32_t sb = sbase + s * SSTAGE;
#pragma unroll
        for (int u = 0; u < 8; u++) {
            int idx = u * 256 + tid;
            int region = idx >> 9;
            int i2 = idx & 511;
            int r = i2 >> 2, c = i2 & 3;
            const __half* base;
            size_t off;
            if (region < 2) {
                int row = n0 + r; if (row > NSEQ - 1) row = NSEQ - 1;
                base = region ? Alo : Ahi;
                off = (size_t)row * KOUT + k0 + c * 8;
            } else {
                base = (region == 3) ? Blo : Bhi;
                off = (size_t)(o0 + r) * KOUT + k0 + c * 8;
            }
            cp16(sb + region * 10240 + r * 80 + c * 16, base + off);
        }
    };

    load_chunk(0, 0);
    CP_COMMIT();

    const int lrow = (lane & 7) + ((lane >> 3) & 1) * 8;
    const int lcol = (lane >> 4) * 8;

    for (int it = 0; it < ONCHUNK; it++) {
        const int cur = it & 1;
        if (it + 1 < ONCHUNK) {
            load_chunk(it + 1, (it + 1) & 1);
            CP_COMMIT();
            CP_WAIT1();
        } else {
            CP_WAIT0();
        }
        __syncthreads();

        const uint32_t sb = sbase + cur * SSTAGE;
#pragma unroll
        for (int ks = 0; ks < 2; ks++) {
            const int colb = (ks * 16 + lcol) * 2;
            uint32_t Bh[4][2], Bl[4][2];
#pragma unroll
            for (int half = 0; half < 2; half++) {
                const int nrow = wn + half * 16 + lrow;
                uint32_t r0, r1, r2, r3;
                ldx4(sb + 20480 + nrow * 80 + colb, r0, r1, r2, r3);
                Bh[half * 2 + 0][0] = r0; Bh[half * 2 + 1][0] = r1;
                Bh[half * 2 + 0][1] = r2; Bh[half * 2 + 1][1] = r3;
                ldx4(sb + 30720 + nrow * 80 + colb, r0, r1, r2, r3);
                Bl[half * 2 + 0][0] = r0; Bl[half * 2 + 1][0] = r1;
                Bl[half * 2 + 0][1] = r2; Bl[half * 2 + 1][1] = r3;
            }
#pragma unroll
            for (int p = 0; p < 2; p++) {
                uint32_t ah[2][4], al[2][4];
#pragma unroll
                for (int m2 = 0; m2 < 2; m2++) {
                    const int mrow = wm + (p * 2 + m2) * 16 + lrow;
                    ldx4(sb + mrow * 80 + colb,
                         ah[m2][0], ah[m2][1], ah[m2][2], ah[m2][3]);
                    ldx4(sb + 10240 + mrow * 80 + colb,
                         al[m2][0], al[m2][1], al[m2][2], al[m2][3]);
                }
#pragma unroll
                for (int m2 = 0; m2 < 2; m2++)
#pragma unroll
                    for (int nj = 0; nj < 4; nj++)
                        mma16816(acc[p * 2 + m2][nj], ah[m2], Bh[nj]);
#pragma unroll
                for (int m2 = 0; m2 < 2; m2++)
#pragma unroll
                    for (int nj = 0; nj < 4; nj++)
                        mma16816(acc[p * 2 + m2][nj], ah[m2], Bl[nj]);
#pragma unroll
                for (int m2 = 0; m2 < 2; m2++)
#pragma unroll
                    for (int nj = 0; nj < 4; nj++)
                        mma16816(acc[p * 2 + m2][nj], al[m2], Bh[nj]);
            }
        }
        __syncthreads();
    }

    const int gq = lane >> 2;
    const int tq = lane & 3;
#pragma unroll
    for (int mi = 0; mi < 4; mi++) {
#pragma unroll
        for (int nj = 0; nj < 4; nj++) {
            int col = o0 + wn + nj * 8 + tq * 2;
            int row0 = n0 + wm + mi * 16 + gq;
            if (row0 < NSEQ)
                *(float2*)(out + ((size_t)b * NSEQ + row0) * HDIM + col) =
                    make_float2(acc[mi][nj][0], acc[mi][nj][1]);
            int row1 = row0 + 8;
            if (row1 < NSEQ)
                *(float2*)(out + ((size_t)b * NSEQ + row1) * HDIM + col) =
                    make_float2(acc[mi][nj][2], acc[mi][nj][3]);
        }
    }
}

// ---------------------------------------------------------------------------
extern "C" void kernel_launch(void* const* d_in, const int* in_sizes, int n_in,
                              void* d_out, int out_size)
{
    const float* input_query = (const float*)d_in[0];
    const float* input_key   = (const float*)d_in[1];
    const float* input_value = (const float*)d_in[2];
    const float* loc_vector  = (const float*)d_in[3];
    const float* Wq   = (const float*)d_in[4];
    const float* bq   = (const float*)d_in[5];
    const float* Wk   = (const float*)d_in[6];
    const float* bk   = (const float*)d_in[7];
    const float* Wv   = (const float*)d_in[8];
    const float* bv   = (const float*)d_in[9];
    const float* Wloc = (const float*)d_in[10];
    const float* bloc = (const float*)d_in[11];
    const float* Wlk  = (const float*)d_in[12];
    const float* blk  = (const float*)d_in[13];
    const float* param = (const float*)d_in[14];
    float* out = (float*)d_out;

    float *q1, *q2, *lk, *kloc, *lv;
    __half *Ah, *Wh;
    cudaGetSymbolAddress((void**)&q1,   g_q1);
    cudaGetSymbolAddress((void**)&q2,   g_q2);
    cudaGetSymbolAddress((void**)&lk,   g_lk);
    cudaGetSymbolAddress((void**)&kloc, g_kloc);
    cudaGetSymbolAddress((void**)&lv,   g_lv);
    cudaGetSymbolAddress((void**)&Ah,   gAh);
    cudaGetSymbolAddress((void**)&Wh,   gWh);

    cudaFuncSetAttribute(proj_mma, cudaFuncAttributeMaxDynamicSharedMemorySize,
                         TSMEM);
    cudaFuncSetAttribute(scores_mma, cudaFuncAttributeMaxDynamicSharedMemorySize,
                         SSMEM);
    cudaFuncSetAttribute(out_mma, cudaFuncAttributeMaxDynamicSharedMemorySize,
                         SSMEM);

    ConvAP CA;
    CA.src[0] = input_query; CA.src[1] = input_key;
    CA.src[2] = input_value; CA.src[3] = loc_vector;
    convA_kernel<<<dim3(200, 16, 4), 256>>>(CA);

    ConvWP CW;
    CW.src[0] = Wq; CW.src[1] = Wloc; CW.src[2] = Wk; CW.src[3] = Wlk; CW.src[4] = Wv;
    convW_kernel<<<dim3(256, 16, 5), 256>>>(CW);

    ProjParams P;
    const int aidx[5] = {0, 3, 1, 3, 2};     // query, loc, key, loc, value
    const float* biases[5] = {bq, bloc, bk, blk, bv};
    float* outs[5] = {q1, q2, lk, kloc, lv};
    for (int g = 0; g < 5; g++) {
        P.A[g]    = Ah + (size_t)aidx[g] * MK;
        P.B[g]    = Wh + (size_t)g * KN;
        P.bias[g] = biases[g];
        P.C[g]    = outs[g];
    }
    proj_mma<<<dim3(HDIM / 128, MTOT / 128, 5), 128, TSMEM>>>(P);

    qkpack_kernel<<<(BATCH * NSEQ * HDIM / 2 + 255) / 256, 256>>>(param);
    lvT_kernel<<<dim3(HDIM / 32, KOUT / 32, BATCH), dim3(32, 8)>>>();

    scores_mma<<<dim3(2, 2, BATCH * 4), 256, SSMEM>>>();
    softmax_kernel<<<BATCH * NSEQ, 256>>>();
    out_mma<<<dim3(HDIM / 128, 2, BATCH), 256, SSMEM>>>(out);
}